// round 2
// baseline (speedup 1.0000x reference)
#include <cuda_runtime.h>
#include <math.h>

#define N_NODES 16384
#define N_EDGES 131072
#define TE 128           // edges per MLP CTA

typedef unsigned long long u64;

// ---------------- scratch (static device arrays: allocation-guard safe) ----
__device__ int   g_counts[N_NODES];
__device__ int   g_cursor[N_NODES];
__device__ int   g_offsets[N_NODES + 1];
__device__ int   g_edge[N_EDGES];
__device__ float g_w[(size_t)N_EDGES * 384];

// ---------------- packed f32x2 helpers --------------------------------------
__device__ __forceinline__ void fma2(u64& acc, u64 a, u64 b) {
    asm("fma.rn.f32x2 %0, %1, %2, %0;" : "+l"(acc) : "l"(a), "l"(b));
}
__device__ __forceinline__ float2 upk(u64 v) {
    float2 f;
    asm("mov.b64 {%0, %1}, %2;" : "=f"(f.x), "=f"(f.y) : "l"(v));
    return f;
}

// ---------------- CSR build ------------------------------------------------
__global__ void k_zero() {
    int i = blockIdx.x * blockDim.x + threadIdx.x;
    if (i < N_NODES) g_counts[i] = 0;
}

__global__ void k_hist(const int* __restrict__ recv) {
    int e = blockIdx.x * blockDim.x + threadIdx.x;
    if (e < N_EDGES) atomicAdd(&g_counts[recv[e]], 1);
}

// single CTA, 1024 threads, 16 counts/thread
__global__ void k_scan() {
    __shared__ int part[1024];
    int t = threadIdx.x;
    int base = t * 16;
    int loc[16];
    int sum = 0;
#pragma unroll
    for (int i = 0; i < 16; i++) { loc[i] = g_counts[base + i]; sum += loc[i]; }
    part[t] = sum;
    __syncthreads();
    for (int off = 1; off < 1024; off <<= 1) {
        int add = (t >= off) ? part[t - off] : 0;
        __syncthreads();
        part[t] += add;
        __syncthreads();
    }
    int run = part[t] - sum;   // exclusive base for this chunk
#pragma unroll
    for (int i = 0; i < 16; i++) {
        g_offsets[base + i] = run;
        run += loc[i];
        g_cursor[base + i] = 0;
    }
    if (t == 1023) g_offsets[N_NODES] = run;
}

__global__ void k_scatter(const int* __restrict__ recv) {
    int e = blockIdx.x * blockDim.x + threadIdx.x;
    if (e < N_EDGES) {
        int r = recv[e];
        int pos = g_offsets[r] + atomicAdd(&g_cursor[r], 1);
        g_edge[pos] = e;
    }
}

// ---------------- per-edge MLP: w = silu(silu(r@W1/s8)@W2/8)@W3 * SC -------
#define SCALE_H1 0.35355339059327373f   // 1/sqrt(8)
#define SCALE_H2 0.125f                 // 1/sqrt(64)
#define SCALE_W  0.04419417382415922f   // 0.125 * (1/sqrt(8))

__device__ __forceinline__ float silu_f(float x) {
    float sg = 1.0f / (1.0f + __expf(-x));
    return x * sg;
}

// smem layout (floats):
//   sw1   [8][64]       512
//   sw2   [64][64]     4096
//   sR    [128][8]     1024
//   sH1d  [64][256]   16384   (H1 duplicated along edges: (v,v) pairs)
//   sH2d  [64][256]   16384   (H2 duplicated)
//   sw3   [64][64]     4096   (current output chunk)
#define SMEM_FLOATS (512 + 4096 + 1024 + 16384 + 16384 + 4096)

__global__ void __launch_bounds__(256) k_mlp(
    const float* __restrict__ radial,
    const float* __restrict__ w1,
    const float* __restrict__ w2,
    const float* __restrict__ w3)
{
    extern __shared__ float sm[];
    float* sw1  = sm;                  //  512
    float* sw2  = sw1 + 512;           // 4096
    float* sR   = sw2 + 4096;          // 1024
    float* sH1d = sR  + 1024;          // 16384
    float* sH2d = sH1d + 16384;        // 16384
    float* sw3  = sH2d + 16384;        // 4096

    int t = threadIdx.x;               // 256 threads
    int ebase = blockIdx.x * TE;

    for (int i = t; i < 512;  i += 256) sw1[i] = w1[i];
    for (int i = t; i < 4096; i += 256) sw2[i] = w2[i];
    for (int i = t; i < TE * 8; i += 256) sR[i] = radial[(size_t)ebase * 8 + i];
    __syncthreads();

    // ---- H1 = silu(R @ W1 * SCALE_H1), written duplicated [j][2e] ----
    for (int idx = t; idx < TE * 64; idx += 256) {
        int j = idx & 63, e = idx >> 6;
        float acc = 0.f;
#pragma unroll
        for (int k = 0; k < 8; k++) acc = fmaf(sR[e * 8 + k], sw1[k * 64 + j], acc);
        float v = silu_f(acc * SCALE_H1);
        *(float2*)&sH1d[j * 256 + 2 * e] = make_float2(v, v);
    }
    __syncthreads();

    int jb = t & 7, eb = t >> 3;       // eb: 0..31, jb: 0..7
    int e4 = eb * 4, j0 = jb * 8;      // thread tile: 4 edges x 8 cols

    // ---- H2 = silu(H1 @ W2 * SCALE_H2) -> sH2d duplicated ----
    {
        u64 acc[4][4];
#pragma unroll
        for (int a = 0; a < 4; a++)
#pragma unroll
            for (int b = 0; b < 4; b++) acc[a][b] = 0ULL;

#pragma unroll 4
        for (int k = 0; k < 64; k++) {
            // A dup-pairs: (a0,a0),(a1,a1),(a2,a2),(a3,a3)
            ulonglong2 A0 = *(const ulonglong2*)&sH1d[k * 256 + 2 * e4];
            ulonglong2 A1 = *(const ulonglong2*)&sH1d[k * 256 + 2 * e4 + 4];
            // B col-pairs: (b0,b1),(b2,b3),(b4,b5),(b6,b7)
            ulonglong2 B0 = *(const ulonglong2*)&sw2[k * 64 + j0];
            ulonglong2 B1 = *(const ulonglong2*)&sw2[k * 64 + j0 + 4];
            u64 ad[4] = {A0.x, A0.y, A1.x, A1.y};
            u64 bp[4] = {B0.x, B0.y, B1.x, B1.y};
#pragma unroll
            for (int a = 0; a < 4; a++)
#pragma unroll
                for (int b = 0; b < 4; b++) fma2(acc[a][b], ad[a], bp[b]);
        }
#pragma unroll
        for (int a = 0; a < 4; a++) {
            int e = e4 + a;
#pragma unroll
            for (int b = 0; b < 4; b++) {
                float2 v = upk(acc[a][b]);
                float s0 = silu_f(v.x * SCALE_H2);
                float s1 = silu_f(v.y * SCALE_H2);
                *(float2*)&sH2d[(j0 + 2 * b)     * 256 + 2 * e] = make_float2(s0, s0);
                *(float2*)&sH2d[(j0 + 2 * b + 1) * 256 + 2 * e] = make_float2(s1, s1);
            }
        }
    }
    __syncthreads();

    // ---- W = H2 @ W3 * SCALE_W, 6 chunks of 64 output cols ----
    for (int c = 0; c < 6; c++) {
        for (int i = t; i < 4096; i += 256) {
            int k = i >> 6, j = i & 63;
            sw3[i] = w3[k * 384 + c * 64 + j];
        }
        __syncthreads();

        u64 acc[4][4];
#pragma unroll
        for (int a = 0; a < 4; a++)
#pragma unroll
            for (int b = 0; b < 4; b++) acc[a][b] = 0ULL;

#pragma unroll 4
        for (int k = 0; k < 64; k++) {
            ulonglong2 A0 = *(const ulonglong2*)&sH2d[k * 256 + 2 * e4];
            ulonglong2 A1 = *(const ulonglong2*)&sH2d[k * 256 + 2 * e4 + 4];
            ulonglong2 B0 = *(const ulonglong2*)&sw3[k * 64 + j0];
            ulonglong2 B1 = *(const ulonglong2*)&sw3[k * 64 + j0 + 4];
            u64 ad[4] = {A0.x, A0.y, A1.x, A1.y};
            u64 bp[4] = {B0.x, B0.y, B1.x, B1.y};
#pragma unroll
            for (int a = 0; a < 4; a++)
#pragma unroll
                for (int b = 0; b < 4; b++) fma2(acc[a][b], ad[a], bp[b]);
        }

#pragma unroll
        for (int a = 0; a < 4; a++) {
            float2 p0 = upk(acc[a][0]);
            float2 p1 = upk(acc[a][1]);
            float2 p2 = upk(acc[a][2]);
            float2 p3 = upk(acc[a][3]);
            size_t e = (size_t)(ebase + e4 + a);
            float* dst = g_w + e * 384 + c * 64 + j0;
            *(float4*)(dst)     = make_float4(p0.x * SCALE_W, p0.y * SCALE_W,
                                              p1.x * SCALE_W, p1.y * SCALE_W);
            *(float4*)(dst + 4) = make_float4(p2.x * SCALE_W, p2.y * SCALE_W,
                                              p3.x * SCALE_W, p3.y * SCALE_W);
        }
        __syncthreads();
    }
}

// ---------------- gather / tensor-product / accumulate ---------------------
// warp per receiver node; lane handles m0 = 2*lane and m0+1
#define INV_SQRT3 0.57735026918962576f

__global__ void __launch_bounds__(256) k_gather(
    const float* __restrict__ nf,
    const float* __restrict__ ef,
    const int*   __restrict__ send,
    float*       __restrict__ out)
{
    int gw = (blockIdx.x * blockDim.x + threadIdx.x) >> 5;
    int lane = threadIdx.x & 31;
    if (gw >= N_NODES) return;

    int beg = g_offsets[gw], end = g_offsets[gw + 1];
    int m0 = lane * 2;

    float s0a = 0.f, s0b = 0.f, s1a = 0.f, s1b = 0.f, s2a = 0.f, s2b = 0.f;
    float v0a0=0.f,v0a1=0.f,v0a2=0.f, v0b0=0.f,v0b1=0.f,v0b2=0.f;
    float v1a0=0.f,v1a1=0.f,v1a2=0.f, v1b0=0.f,v1b1=0.f,v1b2=0.f;
    float v2a0=0.f,v2a1=0.f,v2a2=0.f, v2b0=0.f,v2b1=0.f,v2b2=0.f;

    for (int p = beg; p < end; p++) {
        int e = g_edge[p];
        int s = send[e];
        const float* row = nf + (size_t)s * 256;
        float4 efv = *(const float4*)(ef + (size_t)e * 4);
        float es = efv.x, e0 = efv.y, e1 = efv.z, e2 = efv.w;

        float2 se = *(const float2*)(row + m0);
        float2 va = *(const float2*)(row + 64 + 3 * m0);
        float2 vb = *(const float2*)(row + 66 + 3 * m0);
        float2 vc = *(const float2*)(row + 68 + 3 * m0);

        const float* wr = g_w + (size_t)e * 384;
        float2 w0 = *(const float2*)(wr + m0);
        float2 w1 = *(const float2*)(wr + 64 + m0);
        float2 w2 = *(const float2*)(wr + 128 + m0);
        float2 w3 = *(const float2*)(wr + 192 + m0);
        float2 w4 = *(const float2*)(wr + 256 + m0);
        float2 w5 = *(const float2*)(wr + 320 + m0);

        // m = m0
        {
            float S = se.x, V0 = va.x, V1 = va.y, V2 = vb.x;
            float Ses = S * es;
            s0a = fmaf(S, w0.x, s0a);
            s1a = fmaf(Ses, w1.x, s1a);
            float dot = fmaf(V0, e0, fmaf(V1, e1, V2 * e2));
            s2a = fmaf(dot * INV_SQRT3, w2.x, s2a);
            v0a0 = fmaf(V0, w3.x, v0a0); v0a1 = fmaf(V1, w3.x, v0a1); v0a2 = fmaf(V2, w3.x, v0a2);
            v1a0 = fmaf(S * e0, w4.x, v1a0);
            v1a1 = fmaf(S * e1, w4.x, v1a1);
            v1a2 = fmaf(S * e2, w4.x, v1a2);
            v2a0 = fmaf(V0 * es, w5.x, v2a0); v2a1 = fmaf(V1 * es, w5.x, v2a1); v2a2 = fmaf(V2 * es, w5.x, v2a2);
        }
        // m = m0 + 1
        {
            float S = se.y, V0 = vb.y, V1 = vc.x, V2 = vc.y;
            float Ses = S * es;
            s0b = fmaf(S, w0.y, s0b);
            s1b = fmaf(Ses, w1.y, s1b);
            float dot = fmaf(V0, e0, fmaf(V1, e1, V2 * e2));
            s2b = fmaf(dot * INV_SQRT3, w2.y, s2b);
            v0b0 = fmaf(V0, w3.y, v0b0); v0b1 = fmaf(V1, w3.y, v0b1); v0b2 = fmaf(V2, w3.y, v0b2);
            v1b0 = fmaf(S * e0, w4.y, v1b0); v1b1 = fmaf(S * e1, w4.y, v1b1); v1b2 = fmaf(S * e2, w4.y, v1b2);
            v2b0 = fmaf(V0 * es, w5.y, v2b0); v2b1 = fmaf(V1 * es, w5.y, v2b1); v2b2 = fmaf(V2 * es, w5.y, v2b2);
        }
    }

    float* o = out + (size_t)gw * 768;
    *(float2*)(o + m0)        = make_float2(s0a, s0b);
    *(float2*)(o + 64 + m0)   = make_float2(s1a, s1b);
    *(float2*)(o + 128 + m0)  = make_float2(s2a, s2b);

    {
        int base = 192 + m0 * 3;
        *(float2*)(o + base)     = make_float2(v0a0, v0a1);
        *(float2*)(o + base + 2) = make_float2(v0a2, v0b0);
        *(float2*)(o + base + 4) = make_float2(v0b1, v0b2);
    }
    {
        int base = 192 + (64 + m0) * 3;
        *(float2*)(o + base)     = make_float2(v1a0, v1a1);
        *(float2*)(o + base + 2) = make_float2(v1a2, v1b0);
        *(float2*)(o + base + 4) = make_float2(v1b1, v1b2);
    }
    {
        int base = 192 + (128 + m0) * 3;
        *(float2*)(o + base)     = make_float2(v2a0, v2a1);
        *(float2*)(o + base + 2) = make_float2(v2a2, v2b0);
        *(float2*)(o + base + 4) = make_float2(v2b1, v2b2);
    }
}

// ---------------- launch ----------------------------------------------------
extern "C" void kernel_launch(void* const* d_in, const int* in_sizes, int n_in,
                              void* d_out, int out_size) {
    const float* nf   = (const float*)d_in[0];
    const float* ef   = (const float*)d_in[1];
    const float* rad  = (const float*)d_in[2];
    const float* w1   = (const float*)d_in[3];
    const float* w2   = (const float*)d_in[4];
    const float* w3   = (const float*)d_in[5];
    const int*   send = (const int*)d_in[6];
    const int*   recv = (const int*)d_in[7];
    float* out = (float*)d_out;

    const int smem_mlp = SMEM_FLOATS * 4;  // 169984 B
    cudaFuncSetAttribute(k_mlp, cudaFuncAttributeMaxDynamicSharedMemorySize, smem_mlp);

    k_zero   <<<N_NODES / 256, 256>>>();
    k_hist   <<<N_EDGES / 256, 256>>>(recv);
    k_scan   <<<1, 1024>>>();
    k_scatter<<<N_EDGES / 256, 256>>>(recv);
    k_mlp    <<<N_EDGES / TE, 256, smem_mlp>>>(rad, w1, w2, w3);
    k_gather <<<(N_NODES * 32) / 256, 256>>>(nf, ef, send, out);
}

// round 4
// speedup vs baseline: 2.0687x; 2.0687x over previous
#include <cuda_runtime.h>
#include <cuda_bf16.h>
#include <math.h>
#include <cstdint>

#define N_NODES 16384
#define N_EDGES 131072

typedef uint32_t u32;

// ---------------- scratch (static device arrays) ---------------------------
__device__ int   g_counts[N_NODES];
__device__ int   g_cursor[N_NODES];
__device__ int   g_offsets[N_NODES + 1];
__device__ int   g_edge[N_EDGES];
__device__ float g_w[(size_t)N_EDGES * 384];

// pre-split, transposed (n-major) B operands: [n][k] bf16
__device__ __align__(16) __nv_bfloat16 g_b2hi[64 * 64];
__device__ __align__(16) __nv_bfloat16 g_b2lo[64 * 64];
__device__ __align__(16) __nv_bfloat16 g_b3hi[384 * 64];
__device__ __align__(16) __nv_bfloat16 g_b3lo[384 * 64];

// ---------------- helpers ----------------------------------------------------
__device__ __forceinline__ void mma_bf16(float* c, const u32* a, u32 b0, u32 b1) {
    asm volatile(
        "mma.sync.aligned.m16n8k16.row.col.f32.bf16.bf16.f32 "
        "{%0,%1,%2,%3}, {%4,%5,%6,%7}, {%8,%9}, {%0,%1,%2,%3};"
        : "+f"(c[0]), "+f"(c[1]), "+f"(c[2]), "+f"(c[3])
        : "r"(a[0]), "r"(a[1]), "r"(a[2]), "r"(a[3]), "r"(b0), "r"(b1));
}

__device__ __forceinline__ u32 pk2(__nv_bfloat16 a, __nv_bfloat16 b) {
    __nv_bfloat162 v = __halves2bfloat162(a, b);
    return *(u32*)&v;
}
__device__ __forceinline__ void split_bf(float x, __nv_bfloat16& h, __nv_bfloat16& l) {
    h = __float2bfloat16(x);
    l = __float2bfloat16(x - __bfloat162float(h));
}
__device__ __forceinline__ float silu_f(float x) {
    return x / (1.0f + __expf(-x));
}

#define SCALE_H1 0.35355339059327373f   // 1/sqrt(8)
#define SCALE_H2 0.125f                 // 1/sqrt(64)
#define SCALE_W  0.04419417382415922f   // 0.125 * 1/sqrt(8)
#define INV_SQRT3 0.57735026918962576f

// ---------------- CSR build -------------------------------------------------
__global__ void k_zero() {
    int i = blockIdx.x * blockDim.x + threadIdx.x;
    if (i < N_NODES) g_counts[i] = 0;
}
__global__ void k_hist(const int* __restrict__ recv) {
    int e = blockIdx.x * blockDim.x + threadIdx.x;
    if (e < N_EDGES) atomicAdd(&g_counts[recv[e]], 1);
}
__global__ void k_scan() {
    __shared__ int part[1024];
    int t = threadIdx.x;
    int base = t * 16;
    int loc[16];
    int sum = 0;
#pragma unroll
    for (int i = 0; i < 16; i++) { loc[i] = g_counts[base + i]; sum += loc[i]; }
    part[t] = sum;
    __syncthreads();
    for (int off = 1; off < 1024; off <<= 1) {
        int add = (t >= off) ? part[t - off] : 0;
        __syncthreads();
        part[t] += add;
        __syncthreads();
    }
    int run = part[t] - sum;
#pragma unroll
    for (int i = 0; i < 16; i++) {
        g_offsets[base + i] = run;
        run += loc[i];
        g_cursor[base + i] = 0;
    }
    if (t == 1023) g_offsets[N_NODES] = run;
}
__global__ void k_scatter(const int* __restrict__ recv) {
    int e = blockIdx.x * blockDim.x + threadIdx.x;
    if (e < N_EDGES) {
        int r = recv[e];
        int pos = g_offsets[r] + atomicAdd(&g_cursor[r], 1);
        g_edge[pos] = e;
    }
}

// ---------------- B-operand prep: transpose (n-major) + bf16 split ----------
__global__ void k_prep(const float* __restrict__ w2, const float* __restrict__ w3) {
    int idx = blockIdx.x * 256 + threadIdx.x;       // 448*64 total
    if (idx >= 448 * 64) return;
    int n = idx >> 6, k = idx & 63;
    float v;
    if (n < 64) v = w2[k * 64 + n];
    else        v = w3[k * 384 + (n - 64)];
    __nv_bfloat16 h, l;
    split_bf(v, h, l);
    if (n < 64) {
        g_b2hi[n * 64 + k] = h;
        g_b2lo[n * 64 + k] = l;
    } else {
        int m = n - 64;
        g_b3hi[m * 64 + k] = h;
        g_b3lo[m * 64 + k] = l;
    }
}

// ---------------- MMA MLP ----------------------------------------------------
// smem layout in u32 units; rows padded to 36 u32 (144B) for conflict-free frags
#define STRD 36
#define O_A1HI 0
#define O_A1LO 4608
#define O_A2HI 9216
#define O_A2LO 13824
#define O_B2HI 18432
#define O_B2LO 20736
#define O_B3HI 23040
#define O_B3LO 36864
#define SMEM_U32 50688
#define SMEM_MLP (SMEM_U32 * 4)   // 202752 B

__global__ void __launch_bounds__(256) k_mlp_mma(
    const float* __restrict__ radial,
    const float* __restrict__ w1)
{
    extern __shared__ u32 smu[];
    int t = threadIdx.x, wid = t >> 5, lane = t & 31;
    int qr = lane >> 2, qc = lane & 3;
    int ebase = blockIdx.x * 128;

    // ---- stage B operands into padded smem; w1 into A2 region (temp) ----
    {
        const u32* b2h = (const u32*)g_b2hi;
        const u32* b2l = (const u32*)g_b2lo;
        for (int i = t; i < 2048; i += 256) {
            int n = i >> 5, j = i & 31;
            smu[O_B2HI + n * STRD + j] = b2h[i];
            smu[O_B2LO + n * STRD + j] = b2l[i];
        }
        const u32* b3h = (const u32*)g_b3hi;
        const u32* b3l = (const u32*)g_b3lo;
        for (int i = t; i < 12288; i += 256) {
            int n = i >> 5, j = i & 31;
            smu[O_B3HI + n * STRD + j] = b3h[i];
            smu[O_B3LO + n * STRD + j] = b3l[i];
        }
        float* sw1 = (float*)(smu + O_A2HI);
        for (int i = t; i < 512; i += 256) sw1[i] = w1[i];
    }
    __syncthreads();

    // ---- layer 1 (scalar): H1 = silu(R @ W1 / sqrt8) -> A1hi/A1lo ----
    if (t < 128) {
        const float* sw1 = (const float*)(smu + O_A2HI);
        const float4* rp = (const float4*)(radial + (size_t)(ebase + t) * 8);
        float4 ra = rp[0], rb = rp[1];
        float rr[8] = {ra.x, ra.y, ra.z, ra.w, rb.x, rb.y, rb.z, rb.w};
#pragma unroll
        for (int g = 0; g < 8; g++) {
            float acc[8] = {0, 0, 0, 0, 0, 0, 0, 0};
#pragma unroll
            for (int k = 0; k < 8; k++) {
                float rv = rr[k];
                const float* wrow = sw1 + k * 64 + g * 8;
#pragma unroll
                for (int jj = 0; jj < 8; jj++) acc[jj] = fmaf(rv, wrow[jj], acc[jj]);
            }
#pragma unroll
            for (int p = 0; p < 4; p++) {
                float x0 = silu_f(acc[2 * p]     * SCALE_H1);
                float x1 = silu_f(acc[2 * p + 1] * SCALE_H1);
                __nv_bfloat16 h0, l0, h1, l1;
                split_bf(x0, h0, l0);
                split_bf(x1, h1, l1);
                smu[O_A1HI + t * STRD + g * 4 + p] = pk2(h0, h1);
                smu[O_A1LO + t * STRD + g * 4 + p] = pk2(l0, l1);
            }
        }
    }
    __syncthreads();

    // ---- layer 2 MMA: C2[128x64] = A1 x B2 (3-term split) ----
    int r0 = wid * 16 + qr;     // this thread's primary A row
    u32 ahi[4][4], alo[4][4];
#pragma unroll
    for (int kt = 0; kt < 4; kt++) {
        int o = kt * 8 + qc;
        ahi[kt][0] = smu[O_A1HI + r0 * STRD + o];
        ahi[kt][1] = smu[O_A1HI + (r0 + 8) * STRD + o];
        ahi[kt][2] = smu[O_A1HI + r0 * STRD + o + 4];
        ahi[kt][3] = smu[O_A1HI + (r0 + 8) * STRD + o + 4];
        alo[kt][0] = smu[O_A1LO + r0 * STRD + o];
        alo[kt][1] = smu[O_A1LO + (r0 + 8) * STRD + o];
        alo[kt][2] = smu[O_A1LO + r0 * STRD + o + 4];
        alo[kt][3] = smu[O_A1LO + (r0 + 8) * STRD + o + 4];
    }

    float acc2[8][4];
#pragma unroll
    for (int nt = 0; nt < 8; nt++)
#pragma unroll
        for (int j = 0; j < 4; j++) acc2[nt][j] = 0.f;

#pragma unroll
    for (int nt = 0; nt < 8; nt++) {
        int nrow = nt * 8 + qr;
#pragma unroll
        for (int kt = 0; kt < 4; kt++) {
            int o = nrow * STRD + kt * 8 + qc;
            u32 bh0 = smu[O_B2HI + o], bh1 = smu[O_B2HI + o + 4];
            u32 bl0 = smu[O_B2LO + o], bl1 = smu[O_B2LO + o + 4];
            mma_bf16(acc2[nt], ahi[kt], bh0, bh1);
            mma_bf16(acc2[nt], ahi[kt], bl0, bl1);
            mma_bf16(acc2[nt], alo[kt], bh0, bh1);
        }
    }
    __syncthreads();   // w1 temp (A2 region) fully consumed by all warps

    // epilogue: silu(x/8), split -> A2hi/lo
#pragma unroll
    for (int nt = 0; nt < 8; nt++) {
        int p = nt * 4 + qc;
        float x0 = silu_f(acc2[nt][0] * SCALE_H2);
        float x1 = silu_f(acc2[nt][1] * SCALE_H2);
        float x2 = silu_f(acc2[nt][2] * SCALE_H2);
        float x3 = silu_f(acc2[nt][3] * SCALE_H2);
        __nv_bfloat16 h0, l0, h1, l1, h2, l2, h3, l3;
        split_bf(x0, h0, l0);
        split_bf(x1, h1, l1);
        split_bf(x2, h2, l2);
        split_bf(x3, h3, l3);
        smu[O_A2HI + r0 * STRD + p]       = pk2(h0, h1);
        smu[O_A2LO + r0 * STRD + p]       = pk2(l0, l1);
        smu[O_A2HI + (r0 + 8) * STRD + p] = pk2(h2, h3);
        smu[O_A2LO + (r0 + 8) * STRD + p] = pk2(l2, l3);
    }
    __syncthreads();

    // ---- layer 3 MMA: C3[128x384] = A2 x B3; write g_w directly ----
#pragma unroll
    for (int kt = 0; kt < 4; kt++) {
        int o = kt * 8 + qc;
        ahi[kt][0] = smu[O_A2HI + r0 * STRD + o];
        ahi[kt][1] = smu[O_A2HI + (r0 + 8) * STRD + o];
        ahi[kt][2] = smu[O_A2HI + r0 * STRD + o + 4];
        ahi[kt][3] = smu[O_A2HI + (r0 + 8) * STRD + o + 4];
        alo[kt][0] = smu[O_A2LO + r0 * STRD + o];
        alo[kt][1] = smu[O_A2LO + (r0 + 8) * STRD + o];
        alo[kt][2] = smu[O_A2LO + r0 * STRD + o + 4];
        alo[kt][3] = smu[O_A2LO + (r0 + 8) * STRD + o + 4];
    }

    size_t er0 = (size_t)(ebase + r0) * 384;
    size_t er1 = (size_t)(ebase + r0 + 8) * 384;

#pragma unroll 2
    for (int nt = 0; nt < 48; nt++) {
        int nrow = nt * 8 + qr;
        float acc[4] = {0.f, 0.f, 0.f, 0.f};
#pragma unroll
        for (int kt = 0; kt < 4; kt++) {
            int o = nrow * STRD + kt * 8 + qc;
            u32 bh0 = smu[O_B3HI + o], bh1 = smu[O_B3HI + o + 4];
            u32 bl0 = smu[O_B3LO + o], bl1 = smu[O_B3LO + o + 4];
            mma_bf16(acc, ahi[kt], bh0, bh1);
            mma_bf16(acc, ahi[kt], bl0, bl1);
            mma_bf16(acc, alo[kt], bh0, bh1);
        }
        int col = nt * 8 + qc * 2;
        *(float2*)&g_w[er0 + col] = make_float2(acc[0] * SCALE_W, acc[1] * SCALE_W);
        *(float2*)&g_w[er1 + col] = make_float2(acc[2] * SCALE_W, acc[3] * SCALE_W);
    }
}

// ---------------- gather / tensor-product / accumulate ---------------------
__global__ void __launch_bounds__(256) k_gather(
    const float* __restrict__ nf,
    const float* __restrict__ ef,
    const int*   __restrict__ send,
    float*       __restrict__ out)
{
    int gw = (blockIdx.x * blockDim.x + threadIdx.x) >> 5;
    int lane = threadIdx.x & 31;
    if (gw >= N_NODES) return;

    int beg = g_offsets[gw], end = g_offsets[gw + 1];
    int m0 = lane * 2;

    float s0a = 0.f, s0b = 0.f, s1a = 0.f, s1b = 0.f, s2a = 0.f, s2b = 0.f;
    float v0a0=0.f,v0a1=0.f,v0a2=0.f, v0b0=0.f,v0b1=0.f,v0b2=0.f;
    float v1a0=0.f,v1a1=0.f,v1a2=0.f, v1b0=0.f,v1b1=0.f,v1b2=0.f;
    float v2a0=0.f,v2a1=0.f,v2a2=0.f, v2b0=0.f,v2b1=0.f,v2b2=0.f;

    for (int p = beg; p < end; p++) {
        int e = g_edge[p];
        int s = send[e];
        const float* row = nf + (size_t)s * 256;
        float4 efv = *(const float4*)(ef + (size_t)e * 4);
        float es = efv.x, e0 = efv.y, e1 = efv.z, e2 = efv.w;

        float2 se = *(const float2*)(row + m0);
        float2 va = *(const float2*)(row + 64 + 3 * m0);
        float2 vb = *(const float2*)(row + 66 + 3 * m0);
        float2 vc = *(const float2*)(row + 68 + 3 * m0);

        const float* wr = g_w + (size_t)e * 384;
        float2 w0 = *(const float2*)(wr + m0);
        float2 w1 = *(const float2*)(wr + 64 + m0);
        float2 w2 = *(const float2*)(wr + 128 + m0);
        float2 w3 = *(const float2*)(wr + 192 + m0);
        float2 w4 = *(const float2*)(wr + 256 + m0);
        float2 w5 = *(const float2*)(wr + 320 + m0);

        {
            float S = se.x, V0 = va.x, V1 = va.y, V2 = vb.x;
            float Ses = S * es;
            s0a = fmaf(S, w0.x, s0a);
            s1a = fmaf(Ses, w1.x, s1a);
            float dot = fmaf(V0, e0, fmaf(V1, e1, V2 * e2));
            s2a = fmaf(dot * INV_SQRT3, w2.x, s2a);
            v0a0 = fmaf(V0, w3.x, v0a0); v0a1 = fmaf(V1, w3.x, v0a1); v0a2 = fmaf(V2, w3.x, v0a2);
            v1a0 = fmaf(S * e0, w4.x, v1a0); v1a1 = fmaf(S * e1, w4.x, v1a1); v1a2 = fmaf(S * e2, w4.x, v1a2);
            v2a0 = fmaf(V0 * es, w5.x, v2a0); v2a1 = fmaf(V1 * es, w5.x, v2a1); v2a2 = fmaf(V2 * es, w5.x, v2a2);
        }
        {
            float S = se.y, V0 = vb.y, V1 = vc.x, V2 = vc.y;
            float Ses = S * es;
            s0b = fmaf(S, w0.y, s0b);
            s1b = fmaf(Ses, w1.y, s1b);
            float dot = fmaf(V0, e0, fmaf(V1, e1, V2 * e2));
            s2b = fmaf(dot * INV_SQRT3, w2.y, s2b);
            v0b0 = fmaf(V0, w3.y, v0b0); v0b1 = fmaf(V1, w3.y, v0b1); v0b2 = fmaf(V2, w3.y, v0b2);
            v1b0 = fmaf(S * e0, w4.y, v1b0); v1b1 = fmaf(S * e1, w4.y, v1b1); v1b2 = fmaf(S * e2, w4.y, v1b2);
            v2b0 = fmaf(V0 * es, w5.y, v2b0); v2b1 = fmaf(V1 * es, w5.y, v2b1); v2b2 = fmaf(V2 * es, w5.y, v2b2);
        }
    }

    float* o = out + (size_t)gw * 768;
    *(float2*)(o + m0)       = make_float2(s0a, s0b);
    *(float2*)(o + 64 + m0)  = make_float2(s1a, s1b);
    *(float2*)(o + 128 + m0) = make_float2(s2a, s2b);
    {
        int base = 192 + m0 * 3;
        *(float2*)(o + base)     = make_float2(v0a0, v0a1);
        *(float2*)(o + base + 2) = make_float2(v0a2, v0b0);
        *(float2*)(o + base + 4) = make_float2(v0b1, v0b2);
    }
    {
        int base = 192 + (64 + m0) * 3;
        *(float2*)(o + base)     = make_float2(v1a0, v1a1);
        *(float2*)(o + base + 2) = make_float2(v1a2, v1b0);
        *(float2*)(o + base + 4) = make_float2(v1b1, v1b2);
    }
    {
        int base = 192 + (128 + m0) * 3;
        *(float2*)(o + base)     = make_float2(v2a0, v2a1);
        *(float2*)(o + base + 2) = make_float2(v2a2, v2b0);
        *(float2*)(o + base + 4) = make_float2(v2b1, v2b2);
    }
}

// ---------------- launch ----------------------------------------------------
extern "C" void kernel_launch(void* const* d_in, const int* in_sizes, int n_in,
                              void* d_out, int out_size) {
    const float* nf   = (const float*)d_in[0];
    const float* ef   = (const float*)d_in[1];
    const float* rad  = (const float*)d_in[2];
    const float* w1   = (const float*)d_in[3];
    const float* w2   = (const float*)d_in[4];
    const float* w3   = (const float*)d_in[5];
    const int*   send = (const int*)d_in[6];
    const int*   recv = (const int*)d_in[7];
    float* out = (float*)d_out;

    cudaFuncSetAttribute(k_mlp_mma, cudaFuncAttributeMaxDynamicSharedMemorySize, SMEM_MLP);

    k_zero    <<<N_NODES / 256, 256>>>();
    k_hist    <<<N_EDGES / 256, 256>>>(recv);
    k_scan    <<<1, 1024>>>();
    k_scatter <<<N_EDGES / 256, 256>>>(recv);
    k_prep    <<<(448 * 64 + 255) / 256, 256>>>(w2, w3);
    k_mlp_mma <<<N_EDGES / 128, 256, SMEM_MLP>>>(rad, w1);
    k_gather  <<<(N_NODES * 32) / 256, 256>>>(nf, ef, send, out);
}

// round 5
// speedup vs baseline: 2.1372x; 1.0331x over previous
#include <cuda_runtime.h>
#include <cuda_bf16.h>
#include <math.h>
#include <cstdint>

#define N_NODES 16384
#define N_EDGES 131072

typedef uint32_t u32;

// ---------------- scratch (static device arrays) ---------------------------
__device__ int   g_counts[N_NODES];
__device__ int   g_cursor[N_NODES];
__device__ int   g_offsets[N_NODES + 1];
__device__ int   g_edge[N_EDGES];          // CSR pos -> edge id
__device__ int   g_sendp[N_EDGES];         // CSR pos -> sender node
__device__ float4 g_efp[N_EDGES];          // CSR pos -> edge features
__device__ float g_w[(size_t)N_EDGES * 384];   // CSR-ordered MLP weights

// pre-split, transposed (n-major) B operands: [n][k] bf16
__device__ __align__(16) __nv_bfloat16 g_b2hi[64 * 64];
__device__ __align__(16) __nv_bfloat16 g_b2lo[64 * 64];
__device__ __align__(16) __nv_bfloat16 g_b3hi[384 * 64];
__device__ __align__(16) __nv_bfloat16 g_b3lo[384 * 64];

// ---------------- helpers ----------------------------------------------------
__device__ __forceinline__ void mma_bf16(float* c, const u32* a, u32 b0, u32 b1) {
    asm volatile(
        "mma.sync.aligned.m16n8k16.row.col.f32.bf16.bf16.f32 "
        "{%0,%1,%2,%3}, {%4,%5,%6,%7}, {%8,%9}, {%0,%1,%2,%3};"
        : "+f"(c[0]), "+f"(c[1]), "+f"(c[2]), "+f"(c[3])
        : "r"(a[0]), "r"(a[1]), "r"(a[2]), "r"(a[3]), "r"(b0), "r"(b1));
}

__device__ __forceinline__ u32 pk2(__nv_bfloat16 a, __nv_bfloat16 b) {
    __nv_bfloat162 v = __halves2bfloat162(a, b);
    return *(u32*)&v;
}
__device__ __forceinline__ void split_bf(float x, __nv_bfloat16& h, __nv_bfloat16& l) {
    h = __float2bfloat16(x);
    l = __float2bfloat16(x - __bfloat162float(h));
}
__device__ __forceinline__ float silu_f(float x) {
    return x / (1.0f + __expf(-x));
}

#define SCALE_H1 0.35355339059327373f   // 1/sqrt(8)
#define SCALE_H2 0.125f                 // 1/sqrt(64)
#define SCALE_W  0.04419417382415922f   // 0.125 * 1/sqrt(8)
#define INV_SQRT3 0.57735026918962576f

// ---------------- CSR build -------------------------------------------------
__global__ void k_zero() {
    int i = blockIdx.x * blockDim.x + threadIdx.x;
    if (i < N_NODES) g_counts[i] = 0;
}
__global__ void k_hist(const int* __restrict__ recv) {
    int e = blockIdx.x * blockDim.x + threadIdx.x;
    if (e < N_EDGES) atomicAdd(&g_counts[recv[e]], 1);
}
__global__ void k_scan() {
    __shared__ int part[1024];
    int t = threadIdx.x;
    int base = t * 16;
    int loc[16];
    int sum = 0;
#pragma unroll
    for (int i = 0; i < 16; i++) { loc[i] = g_counts[base + i]; sum += loc[i]; }
    part[t] = sum;
    __syncthreads();
    for (int off = 1; off < 1024; off <<= 1) {
        int add = (t >= off) ? part[t - off] : 0;
        __syncthreads();
        part[t] += add;
        __syncthreads();
    }
    int run = part[t] - sum;
#pragma unroll
    for (int i = 0; i < 16; i++) {
        g_offsets[base + i] = run;
        run += loc[i];
        g_cursor[base + i] = 0;
    }
    if (t == 1023) g_offsets[N_NODES] = run;
}
__global__ void k_scatter(const int* __restrict__ recv,
                          const int* __restrict__ send,
                          const float* __restrict__ ef) {
    int e = blockIdx.x * blockDim.x + threadIdx.x;
    if (e < N_EDGES) {
        int r = recv[e];
        int pos = g_offsets[r] + atomicAdd(&g_cursor[r], 1);
        g_edge[pos] = e;
        g_sendp[pos] = send[e];
        g_efp[pos] = *(const float4*)(ef + (size_t)e * 4);
    }
}

// ---------------- B-operand prep: transpose (n-major) + bf16 split ----------
__global__ void k_prep(const float* __restrict__ w2, const float* __restrict__ w3) {
    int idx = blockIdx.x * 256 + threadIdx.x;       // 448*64 total
    if (idx >= 448 * 64) return;
    int n = idx >> 6, k = idx & 63;
    float v;
    if (n < 64) v = w2[k * 64 + n];
    else        v = w3[k * 384 + (n - 64)];
    __nv_bfloat16 h, l;
    split_bf(v, h, l);
    if (n < 64) {
        g_b2hi[n * 64 + k] = h;
        g_b2lo[n * 64 + k] = l;
    } else {
        int m = n - 64;
        g_b3hi[m * 64 + k] = h;
        g_b3lo[m * 64 + k] = l;
    }
}

// ---------------- MMA MLP (processes CSR positions) -------------------------
// smem layout in u32 units; rows padded to 36 u32 (144B) for conflict-free frags
#define STRD 36
#define O_A1HI 0
#define O_A1LO 4608
#define O_A2HI 9216
#define O_A2LO 13824
#define O_B2HI 18432
#define O_B2LO 20736
#define O_B3HI 23040
#define O_B3LO 36864
#define SMEM_U32 50688
#define SMEM_MLP (SMEM_U32 * 4)   // 202752 B

__global__ void __launch_bounds__(256) k_mlp_mma(
    const float* __restrict__ radial,
    const float* __restrict__ w1)
{
    extern __shared__ u32 smu[];
    int t = threadIdx.x, wid = t >> 5, lane = t & 31;
    int qr = lane >> 2, qc = lane & 3;
    int ebase = blockIdx.x * 128;

    // ---- stage B operands into padded smem; w1 into A2 region (temp) ----
    {
        const u32* b2h = (const u32*)g_b2hi;
        const u32* b2l = (const u32*)g_b2lo;
        for (int i = t; i < 2048; i += 256) {
            int n = i >> 5, j = i & 31;
            smu[O_B2HI + n * STRD + j] = b2h[i];
            smu[O_B2LO + n * STRD + j] = b2l[i];
        }
        const u32* b3h = (const u32*)g_b3hi;
        const u32* b3l = (const u32*)g_b3lo;
        for (int i = t; i < 12288; i += 256) {
            int n = i >> 5, j = i & 31;
            smu[O_B3HI + n * STRD + j] = b3h[i];
            smu[O_B3LO + n * STRD + j] = b3l[i];
        }
        float* sw1 = (float*)(smu + O_A2HI);
        for (int i = t; i < 512; i += 256) sw1[i] = w1[i];
    }
    __syncthreads();

    // ---- layer 1 (scalar): H1 = silu(R[g_edge[p]] @ W1 / sqrt8) ----
    if (t < 128) {
        const float* sw1 = (const float*)(smu + O_A2HI);
        int e = g_edge[ebase + t];
        const float4* rp = (const float4*)(radial + (size_t)e * 8);
        float4 ra = rp[0], rb = rp[1];
        float rr[8] = {ra.x, ra.y, ra.z, ra.w, rb.x, rb.y, rb.z, rb.w};
#pragma unroll
        for (int g = 0; g < 8; g++) {
            float acc[8] = {0, 0, 0, 0, 0, 0, 0, 0};
#pragma unroll
            for (int k = 0; k < 8; k++) {
                float rv = rr[k];
                const float* wrow = sw1 + k * 64 + g * 8;
#pragma unroll
                for (int jj = 0; jj < 8; jj++) acc[jj] = fmaf(rv, wrow[jj], acc[jj]);
            }
#pragma unroll
            for (int p = 0; p < 4; p++) {
                float x0 = silu_f(acc[2 * p]     * SCALE_H1);
                float x1 = silu_f(acc[2 * p + 1] * SCALE_H1);
                __nv_bfloat16 h0, l0, h1, l1;
                split_bf(x0, h0, l0);
                split_bf(x1, h1, l1);
                smu[O_A1HI + t * STRD + g * 4 + p] = pk2(h0, h1);
                smu[O_A1LO + t * STRD + g * 4 + p] = pk2(l0, l1);
            }
        }
    }
    __syncthreads();

    // ---- layer 2 MMA: C2[128x64] = A1 x B2 (3-term split) ----
    int r0 = wid * 16 + qr;
    u32 ahi[4][4], alo[4][4];
#pragma unroll
    for (int kt = 0; kt < 4; kt++) {
        int o = kt * 8 + qc;
        ahi[kt][0] = smu[O_A1HI + r0 * STRD + o];
        ahi[kt][1] = smu[O_A1HI + (r0 + 8) * STRD + o];
        ahi[kt][2] = smu[O_A1HI + r0 * STRD + o + 4];
        ahi[kt][3] = smu[O_A1HI + (r0 + 8) * STRD + o + 4];
        alo[kt][0] = smu[O_A1LO + r0 * STRD + o];
        alo[kt][1] = smu[O_A1LO + (r0 + 8) * STRD + o];
        alo[kt][2] = smu[O_A1LO + r0 * STRD + o + 4];
        alo[kt][3] = smu[O_A1LO + (r0 + 8) * STRD + o + 4];
    }

    float acc2[8][4];
#pragma unroll
    for (int nt = 0; nt < 8; nt++)
#pragma unroll
        for (int j = 0; j < 4; j++) acc2[nt][j] = 0.f;

#pragma unroll
    for (int nt = 0; nt < 8; nt++) {
        int nrow = nt * 8 + qr;
#pragma unroll
        for (int kt = 0; kt < 4; kt++) {
            int o = nrow * STRD + kt * 8 + qc;
            u32 bh0 = smu[O_B2HI + o], bh1 = smu[O_B2HI + o + 4];
            u32 bl0 = smu[O_B2LO + o], bl1 = smu[O_B2LO + o + 4];
            mma_bf16(acc2[nt], ahi[kt], bh0, bh1);
            mma_bf16(acc2[nt], ahi[kt], bl0, bl1);
            mma_bf16(acc2[nt], alo[kt], bh0, bh1);
        }
    }
    __syncthreads();

    // epilogue: silu(x/8), split -> A2hi/lo
#pragma unroll
    for (int nt = 0; nt < 8; nt++) {
        int p = nt * 4 + qc;
        float x0 = silu_f(acc2[nt][0] * SCALE_H2);
        float x1 = silu_f(acc2[nt][1] * SCALE_H2);
        float x2 = silu_f(acc2[nt][2] * SCALE_H2);
        float x3 = silu_f(acc2[nt][3] * SCALE_H2);
        __nv_bfloat16 h0, l0, h1, l1, h2, l2, h3, l3;
        split_bf(x0, h0, l0);
        split_bf(x1, h1, l1);
        split_bf(x2, h2, l2);
        split_bf(x3, h3, l3);
        smu[O_A2HI + r0 * STRD + p]       = pk2(h0, h1);
        smu[O_A2LO + r0 * STRD + p]       = pk2(l0, l1);
        smu[O_A2HI + (r0 + 8) * STRD + p] = pk2(h2, h3);
        smu[O_A2LO + (r0 + 8) * STRD + p] = pk2(l2, l3);
    }
    __syncthreads();

    // ---- layer 3 MMA: C3[128x384] = A2 x B3; write g_w (CSR order) ----
#pragma unroll
    for (int kt = 0; kt < 4; kt++) {
        int o = kt * 8 + qc;
        ahi[kt][0] = smu[O_A2HI + r0 * STRD + o];
        ahi[kt][1] = smu[O_A2HI + (r0 + 8) * STRD + o];
        ahi[kt][2] = smu[O_A2HI + r0 * STRD + o + 4];
        ahi[kt][3] = smu[O_A2HI + (r0 + 8) * STRD + o + 4];
        alo[kt][0] = smu[O_A2LO + r0 * STRD + o];
        alo[kt][1] = smu[O_A2LO + (r0 + 8) * STRD + o];
        alo[kt][2] = smu[O_A2LO + r0 * STRD + o + 4];
        alo[kt][3] = smu[O_A2LO + (r0 + 8) * STRD + o + 4];
    }

    size_t er0 = (size_t)(ebase + r0) * 384;
    size_t er1 = (size_t)(ebase + r0 + 8) * 384;

#pragma unroll 2
    for (int nt = 0; nt < 48; nt++) {
        int nrow = nt * 8 + qr;
        float acc[4] = {0.f, 0.f, 0.f, 0.f};
#pragma unroll
        for (int kt = 0; kt < 4; kt++) {
            int o = nrow * STRD + kt * 8 + qc;
            u32 bh0 = smu[O_B3HI + o], bh1 = smu[O_B3HI + o + 4];
            u32 bl0 = smu[O_B3LO + o], bl1 = smu[O_B3LO + o + 4];
            mma_bf16(acc, ahi[kt], bh0, bh1);
            mma_bf16(acc, ahi[kt], bl0, bl1);
            mma_bf16(acc, alo[kt], bh0, bh1);
        }
        int col = nt * 8 + qc * 2;
        *(float2*)&g_w[er0 + col] = make_float2(acc[0] * SCALE_W, acc[1] * SCALE_W);
        *(float2*)&g_w[er1 + col] = make_float2(acc[2] * SCALE_W, acc[3] * SCALE_W);
    }
}

// ---------------- gather / tensor-product / accumulate ---------------------
// warp per receiver node; all edge-side streams are CSR-ordered (sequential)
__global__ void __launch_bounds__(256) k_gather(
    const float* __restrict__ nf,
    float*       __restrict__ out)
{
    int gw = (blockIdx.x * blockDim.x + threadIdx.x) >> 5;
    int lane = threadIdx.x & 31;
    if (gw >= N_NODES) return;

    int beg = g_offsets[gw], end = g_offsets[gw + 1];
    int m0 = lane * 2;

    float s0a = 0.f, s0b = 0.f, s1a = 0.f, s1b = 0.f, s2a = 0.f, s2b = 0.f;
    float v0a0=0.f,v0a1=0.f,v0a2=0.f, v0b0=0.f,v0b1=0.f,v0b2=0.f;
    float v1a0=0.f,v1a1=0.f,v1a2=0.f, v1b0=0.f,v1b1=0.f,v1b2=0.f;
    float v2a0=0.f,v2a1=0.f,v2a2=0.f, v2b0=0.f,v2b1=0.f,v2b2=0.f;

    for (int p = beg; p < end; p++) {
        int s = g_sendp[p];
        float4 efv = g_efp[p];
        float es = efv.x, e0 = efv.y, e1 = efv.z, e2 = efv.w;

        const float* row = nf + (size_t)s * 256;
        float2 se = *(const float2*)(row + m0);
        float2 va = *(const float2*)(row + 64 + 3 * m0);
        float2 vb = *(const float2*)(row + 66 + 3 * m0);
        float2 vc = *(const float2*)(row + 68 + 3 * m0);

        const float* wr = g_w + (size_t)p * 384;
        float2 w0 = __ldcs((const float2*)(wr + m0));
        float2 w1 = __ldcs((const float2*)(wr + 64 + m0));
        float2 w2 = __ldcs((const float2*)(wr + 128 + m0));
        float2 w3 = __ldcs((const float2*)(wr + 192 + m0));
        float2 w4 = __ldcs((const float2*)(wr + 256 + m0));
        float2 w5 = __ldcs((const float2*)(wr + 320 + m0));

        {
            float S = se.x, V0 = va.x, V1 = va.y, V2 = vb.x;
            float Ses = S * es;
            s0a = fmaf(S, w0.x, s0a);
            s1a = fmaf(Ses, w1.x, s1a);
            float dot = fmaf(V0, e0, fmaf(V1, e1, V2 * e2));
            s2a = fmaf(dot * INV_SQRT3, w2.x, s2a);
            v0a0 = fmaf(V0, w3.x, v0a0); v0a1 = fmaf(V1, w3.x, v0a1); v0a2 = fmaf(V2, w3.x, v0a2);
            v1a0 = fmaf(S * e0, w4.x, v1a0); v1a1 = fmaf(S * e1, w4.x, v1a1); v1a2 = fmaf(S * e2, w4.x, v1a2);
            v2a0 = fmaf(V0 * es, w5.x, v2a0); v2a1 = fmaf(V1 * es, w5.x, v2a1); v2a2 = fmaf(V2 * es, w5.x, v2a2);
        }
        {
            float S = se.y, V0 = vb.y, V1 = vc.x, V2 = vc.y;
            float Ses = S * es;
            s0b = fmaf(S, w0.y, s0b);
            s1b = fmaf(Ses, w1.y, s1b);
            float dot = fmaf(V0, e0, fmaf(V1, e1, V2 * e2));
            s2b = fmaf(dot * INV_SQRT3, w2.y, s2b);
            v0b0 = fmaf(V0, w3.y, v0b0); v0b1 = fmaf(V1, w3.y, v0b1); v0b2 = fmaf(V2, w3.y, v0b2);
            v1b0 = fmaf(S * e0, w4.y, v1b0); v1b1 = fmaf(S * e1, w4.y, v1b1); v1b2 = fmaf(S * e2, w4.y, v1b2);
            v2b0 = fmaf(V0 * es, w5.y, v2b0); v2b1 = fmaf(V1 * es, w5.y, v2b1); v2b2 = fmaf(V2 * es, w5.y, v2b2);
        }
    }

    float* o = out + (size_t)gw * 768;
    *(float2*)(o + m0)       = make_float2(s0a, s0b);
    *(float2*)(o + 64 + m0)  = make_float2(s1a, s1b);
    *(float2*)(o + 128 + m0) = make_float2(s2a, s2b);
    {
        int base = 192 + m0 * 3;
        *(float2*)(o + base)     = make_float2(v0a0, v0a1);
        *(float2*)(o + base + 2) = make_float2(v0a2, v0b0);
        *(float2*)(o + base + 4) = make_float2(v0b1, v0b2);
    }
    {
        int base = 192 + (64 + m0) * 3;
        *(float2*)(o + base)     = make_float2(v1a0, v1a1);
        *(float2*)(o + base + 2) = make_float2(v1a2, v1b0);
        *(float2*)(o + base + 4) = make_float2(v1b1, v1b2);
    }
    {
        int base = 192 + (128 + m0) * 3;
        *(float2*)(o + base)     = make_float2(v2a0, v2a1);
        *(float2*)(o + base + 2) = make_float2(v2a2, v2b0);
        *(float2*)(o + base + 4) = make_float2(v2b1, v2b2);
    }
}

// ---------------- launch ----------------------------------------------------
extern "C" void kernel_launch(void* const* d_in, const int* in_sizes, int n_in,
                              void* d_out, int out_size) {
    const float* nf   = (const float*)d_in[0];
    const float* ef   = (const float*)d_in[1];
    const float* rad  = (const float*)d_in[2];
    const float* w1   = (const float*)d_in[3];
    const float* w2   = (const float*)d_in[4];
    const float* w3   = (const float*)d_in[5];
    const int*   send = (const int*)d_in[6];
    const int*   recv = (const int*)d_in[7];
    float* out = (float*)d_out;

    cudaFuncSetAttribute(k_mlp_mma, cudaFuncAttributeMaxDynamicSharedMemorySize, SMEM_MLP);

    k_zero    <<<N_NODES / 256, 256>>>();
    k_hist    <<<N_EDGES / 256, 256>>>(recv);
    k_scan    <<<1, 1024>>>();
    k_scatter <<<N_EDGES / 256, 256>>>(recv, send, ef);
    k_prep    <<<(448 * 64 + 255) / 256, 256>>>(w2, w3);
    k_mlp_mma <<<N_EDGES / 128, 256, SMEM_MLP>>>(rad, w1);
    k_gather  <<<(N_NODES * 32) / 256, 256>>>(nf, out);
}